// round 16
// baseline (speedup 1.0000x reference)
#include <cuda_runtime.h>
#include <cuda_bf16.h>
#include <math.h>

#define TT 256
#define BSZ 256

// ---------------- device scratch (no allocation APIs) ----------------
static __device__ float g_xg0f[33554432];   // [T*B][512]
static __device__ float g_xg0r[33554432];   // [T*B][512]
static __device__ float g_xg1 [67108864];   // [T*B][1024] (layer1, reused layer2)
static __device__ float g_bl  [16777216];   // [T*B][256]  bilstm h -> LN1 in place
static __device__ float g_h1  [16777216];   // [T*B][256]  layer1 h -> LN2 in place
static __device__ float g_h2  [16777216];   // [T*B][256]  layer2 h
static __device__ int   g_flags[131072];    // per-CTA step flags

__global__ void zero_flags_kernel() {
    int i = blockIdx.x * blockDim.x + threadIdx.x;
    if (i < 131072) g_flags[i] = 0;
}

// ---------------- tf32 helpers (input-projection GEMMs) ----------------
__device__ __forceinline__ unsigned f2tf32(float x) {
    unsigned r;
    asm("cvt.rna.tf32.f32 %0, %1;" : "=r"(r) : "f"(x));
    return r;
}
__device__ __forceinline__ void mma_tf32(float c[4], const unsigned a[4], const unsigned b[2]) {
    asm volatile(
        "mma.sync.aligned.m16n8k8.row.col.f32.tf32.tf32.f32 "
        "{%0,%1,%2,%3}, {%4,%5,%6,%7}, {%8,%9}, {%0,%1,%2,%3};"
        : "+f"(c[0]), "+f"(c[1]), "+f"(c[2]), "+f"(c[3])
        : "r"(a[0]), "r"(a[1]), "r"(a[2]), "r"(a[3]), "r"(b[0]), "r"(b[1]));
}

// ---------------- bf16 helpers (recurrent scans) ----------------
__device__ __forceinline__ void mma_bf16(float c[4], const unsigned* a, const unsigned* b) {
    asm volatile(
        "mma.sync.aligned.m16n8k16.row.col.f32.bf16.bf16.f32 "
        "{%0,%1,%2,%3}, {%4,%5,%6,%7}, {%8,%9}, {%0,%1,%2,%3};"
        : "+f"(c[0]), "+f"(c[1]), "+f"(c[2]), "+f"(c[3])
        : "r"(a[0]), "r"(a[1]), "r"(a[2]), "r"(a[3]), "r"(b[0]), "r"(b[1]));
}
__device__ __forceinline__ void split2(float a, float b, unsigned& hi, unsigned& lo) {
    __nv_bfloat162 h = __floats2bfloat162_rn(a, b);
    float2 hf = __bfloat1622float2(h);
    __nv_bfloat162 l = __floats2bfloat162_rn(a - hf.x, b - hf.y);
    hi = *(unsigned*)&h;
    lo = *(unsigned*)&l;
}

// XOR-swizzled word offsets: row strides 64/128/32, all ≡0 mod 32
#define OW0(r, w) ((r) * 64  + ((w) ^ ((((r) & 7)) << 2)))
#define OW1(r, w) ((r) * 128 + ((w) ^ ((((r) & 7)) << 2)))
#define OWG(r, k) ((r) * 32 + (((((k) >> 2) ^ ((r) & 7))) << 2) + ((k) & 3))

// ---------------- fast transcendentals ----------------
__device__ __forceinline__ float fast_sig(float x) {
    return __fdividef(1.f, 1.f + __expf(-x));
}
__device__ __forceinline__ float fast_tanh(float x) {
    float t = __expf(-2.f * fabsf(x));
    float r = __fdividef(1.f - t, 1.f + t);
    return copysignf(r, x);
}

// ---------------- handshake primitives ----------------
__device__ __forceinline__ void flag_release(int* p) {
    asm volatile("st.release.gpu.s32 [%0], %1;" :: "l"(p), "r"(1) : "memory");
}
__device__ __forceinline__ int flag_acquire(const int* p) {
    int v;
    asm volatile("ld.acquire.gpu.s32 %0, [%1];" : "=r"(v) : "l"(p));
    return v;
}
template<int NC>
__device__ __forceinline__ void spin_wait(const int* fp, int lane) {
    int done = 0;
    do {
        int v = 1;
        if (lane < NC) v = flag_acquire(fp + lane);
        done = __all_sync(0xffffffffu, v != 0);
    } while (!done);
}

// ---------------- cp.async helpers ----------------
__device__ __forceinline__ void cp16(float* dst_smem, const float* src) {
    unsigned d = (unsigned)__cvta_generic_to_shared(dst_smem);
    asm volatile("cp.async.cg.shared.global [%0], [%1], 16;" :: "r"(d), "l"(src));
}
#define CP_COMMIT() asm volatile("cp.async.commit_group;")
#define CP_WAIT(n)  asm volatile("cp.async.wait_group %0;" :: "n"(n))

// ---------------- tf32 GEMM, cp.async 2-stage double buffer ----------------
template<int K, int N, int MODE>
__global__ void __launch_bounds__(256) mma_gemm(const float* __restrict__ Ap,
                                                const float* __restrict__ W,
                                                const float* __restrict__ bias)
{
    extern __shared__ float smg[];
    float* AsF = smg;            // [2][4096]
    float* BsF = smg + 8192;     // [2][4096]

    const int tid = threadIdx.x, lane = tid & 31, wid = tid >> 5;
    const int warpM = wid >> 1, warpN = wid & 1;
    const int cRow = blockIdx.x, cCol = blockIdx.y;

    float acc[2][8][4];
#pragma unroll
    for (int mt = 0; mt < 2; mt++)
#pragma unroll
        for (int nt = 0; nt < 8; nt++)
#pragma unroll
            for (int i = 0; i < 4; i++) acc[mt][nt][i] = 0.f;

    auto stage = [&](int kt, int bf) {
#pragma unroll
        for (int i = 0; i < 4; i++) {
            int f = tid + i * 256;
            int row = f >> 3, c = f & 7;
            const float* ap;
            if (MODE <= 1) {
                int m = cRow * 128 + row;
                ap = Ap + ((size_t)(m & 255) * TT + (m >> 8)) * 128 + kt + c * 4;
            } else if (MODE == 2) {
                ap = g_bl + (size_t)(cRow * 128 + row) * K + kt + c * 4;
            } else {
                ap = g_h1 + (size_t)(cRow * 128 + row) * K + kt + c * 4;
            }
            const float* bp = W + (size_t)(cCol * 128 + row) * K + kt + c * 4;
            int wo = row * 32 + ((c ^ (row & 7)) << 2);
            cp16(&AsF[bf * 4096 + wo], ap);
            cp16(&BsF[bf * 4096 + wo], bp);
        }
        CP_COMMIT();
    };

    stage(0, 0);
    int bf = 0;
    for (int kt = 0; kt < K; kt += 32) {
        if (kt + 32 < K) { stage(kt + 32, bf ^ 1); CP_WAIT(1); }
        else             { CP_WAIT(0); }
        __syncthreads();

        const float* Ab = &AsF[bf * 4096];
        const float* Bb = &BsF[bf * 4096];
#pragma unroll
        for (int kk = 0; kk < 32; kk += 8) {
            const int k0 = kk + (lane & 3);
            unsigned a[2][4], b[8][2];
#pragma unroll
            for (int mt = 0; mt < 2; mt++) {
                int row = warpM * 32 + mt * 16 + (lane >> 2);
                a[mt][0] = f2tf32(Ab[OWG(row, k0)]);
                a[mt][1] = f2tf32(Ab[OWG(row + 8, k0)]);
                a[mt][2] = f2tf32(Ab[OWG(row, k0 + 4)]);
                a[mt][3] = f2tf32(Ab[OWG(row + 8, k0 + 4)]);
            }
#pragma unroll
            for (int nt = 0; nt < 8; nt++) {
                int col = warpN * 64 + nt * 8 + (lane >> 2);
                b[nt][0] = f2tf32(Bb[OWG(col, k0)]);
                b[nt][1] = f2tf32(Bb[OWG(col, k0 + 4)]);
            }
#pragma unroll
            for (int mt = 0; mt < 2; mt++)
#pragma unroll
                for (int nt = 0; nt < 8; nt++)
                    mma_tf32(acc[mt][nt], a[mt], b[nt]);
        }
        __syncthreads();
        bf ^= 1;
    }

    float* Cout = (MODE == 0) ? g_xg0f : (MODE == 1) ? g_xg0r : g_xg1;
#pragma unroll
    for (int nt = 0; nt < 8; nt++) {
        int c = cCol * 128 + warpN * 64 + nt * 8 + (lane & 3) * 2;
        float bx = bias[c], by = bias[c + 1];
#pragma unroll
        for (int mt = 0; mt < 2; mt++) {
            int r0 = cRow * 128 + warpM * 32 + mt * 16 + (lane >> 2);
            float2 o0 = {acc[mt][nt][0] + bx, acc[mt][nt][1] + by};
            float2 o1 = {acc[mt][nt][2] + bx, acc[mt][nt][3] + by};
            *(float2*)(Cout + (size_t)r0 * N + c)       = o0;
            *(float2*)(Cout + (size_t)(r0 + 8) * N + c) = o1;
        }
    }
}

// ---------------- layer0 persistent scan, H=128, grid (16,4,2) ----------------
__global__ void __launch_bounds__(256) scan0_kernel(const float* __restrict__ WhhF,
                                                    const float* __restrict__ WhhR)
{
    const int bi = blockIdx.x, jj = blockIdx.y, dir = blockIdx.z;
    const int tid = threadIdx.x, lane = tid & 31, w = tid >> 5;
    const int j0 = jj * 32, b0 = bi * 16;

    extern __shared__ unsigned smu[];
    unsigned* Wh = smu;                    // 128 rows x 64 words
    unsigned* Wl = Wh + 8192;
    unsigned* Hh = Wl + 8192;              // 16 rows x 64 words
    unsigned* Hl = Hh + 1024;
    float*    Gs = (float*)(Hl + 1024);    // [16][132]

    const float* Whh = dir ? WhhR : WhhF;
    const float* xg  = dir ? g_xg0r : g_xg0f;
    int* fb = g_flags + (dir * 16 + bi) * 1024;   // [256 steps][4 CTAs]

#pragma unroll
    for (int i = 0; i < 16; i++) {
        int v = tid + i * 256;
        int r = v >> 5, k4 = v & 31;
        int jl = r >> 2, g = r & 3;
        float4 wv = *(const float4*)(Whh + (size_t)(g * 128 + j0 + jl) * 128 + k4 * 4);
        int wo = r * 64 + (((k4 * 2) ^ ((r & 7) << 2)));
        unsigned h0, l0, h1, l1;
        split2(wv.x, wv.y, h0, l0);
        split2(wv.z, wv.w, h1, l1);
        *(uint2*)&Wh[wo] = make_uint2(h0, h1);
        *(uint2*)&Wl[wo] = make_uint2(l0, l1);
    }
    __syncthreads();

    const int nt0 = w * 2;
    const int bl = tid >> 4;
    const int jlA = tid & 15;
    float cA = 0.f, cB = 0.f;

    for (int s = 0; s < 256; s++) {
        const int t = dir ? (255 - s) : s;

        float xa[4], xb[4];
        {
            const float* xr = xg + ((size_t)(t * 256 + b0 + bl)) * 512 + j0;
#pragma unroll
            for (int g = 0; g < 4; g++) { xa[g] = xr[(g << 7) + jlA]; xb[g] = xr[(g << 7) + jlA + 16]; }
        }

        if (s > 0) {
            const int tp = dir ? (t + 1) : (t - 1);
            if (w == 0) spin_wait<4>(fb + (s - 1) * 4, lane);
            __syncthreads();
#pragma unroll
            for (int i = 0; i < 2; i++) {
                int v = tid + i * 256;
                int r = v >> 5, k4 = v & 31;
                float4 hv = *(const float4*)(g_bl + ((size_t)(tp * 256 + b0 + r)) * 256 + (dir << 7) + k4 * 4);
                int wo = r * 64 + (((k4 * 2) ^ ((r & 7) << 2)));
                unsigned h0, l0, h1, l1;
                split2(hv.x, hv.y, h0, l0);
                split2(hv.z, hv.w, h1, l1);
                *(uint2*)&Hh[wo] = make_uint2(h0, h1);
                *(uint2*)&Hl[wo] = make_uint2(l0, l1);
            }
            __syncthreads();

            // 3-term split with INDEPENDENT accumulators: per-ks the 6 mma form
            // 6 parallel chains (depth 8) instead of 2 chains of depth 24.
            float ac_hh[2][4] = {{0,0,0,0},{0,0,0,0}};
            float ac_hl[2][4] = {{0,0,0,0},{0,0,0,0}};
            float ac_lh[2][4] = {{0,0,0,0},{0,0,0,0}};
            unsigned fA[2][8], fB[2][8];
            auto loadf = [&](int ks, int buf) {
                const int kw = ks * 8 + (lane & 3);
                const int ra = lane >> 2;
                fA[buf][0] = Hh[OW0(ra, kw)];     fA[buf][1] = Hh[OW0(ra + 8, kw)];
                fA[buf][2] = Hh[OW0(ra, kw + 4)]; fA[buf][3] = Hh[OW0(ra + 8, kw + 4)];
                fA[buf][4] = Hl[OW0(ra, kw)];     fA[buf][5] = Hl[OW0(ra + 8, kw)];
                fA[buf][6] = Hl[OW0(ra, kw + 4)]; fA[buf][7] = Hl[OW0(ra + 8, kw + 4)];
                const int nr0 = nt0 * 8 + (lane >> 2), nr1 = (nt0 + 1) * 8 + (lane >> 2);
                fB[buf][0] = Wh[OW0(nr0, kw)]; fB[buf][1] = Wh[OW0(nr0, kw + 4)];
                fB[buf][2] = Wl[OW0(nr0, kw)]; fB[buf][3] = Wl[OW0(nr0, kw + 4)];
                fB[buf][4] = Wh[OW0(nr1, kw)]; fB[buf][5] = Wh[OW0(nr1, kw + 4)];
                fB[buf][6] = Wl[OW0(nr1, kw)]; fB[buf][7] = Wl[OW0(nr1, kw + 4)];
            };
            loadf(0, 0);
#pragma unroll
            for (int ks = 0; ks < 8; ks++) {
                const int cb = ks & 1;
                if (ks < 7) loadf(ks + 1, cb ^ 1);
                const unsigned* A = fA[cb];
                const unsigned* B = fB[cb];
                mma_bf16(ac_hh[0], A,     B);
                mma_bf16(ac_hl[0], A,     B + 2);
                mma_bf16(ac_lh[0], A + 4, B);
                mma_bf16(ac_hh[1], A,     B + 4);
                mma_bf16(ac_hl[1], A,     B + 6);
                mma_bf16(ac_lh[1], A + 4, B + 4);
            }
#pragma unroll
            for (int n = 0; n < 2; n++) {
                int col = (nt0 + n) * 8 + 2 * (lane & 3);
                int r = lane >> 2;
                Gs[r * 132 + col]           = ac_hh[n][0] + ac_hl[n][0] + ac_lh[n][0];
                Gs[r * 132 + col + 1]       = ac_hh[n][1] + ac_hl[n][1] + ac_lh[n][1];
                Gs[(r + 8) * 132 + col]     = ac_hh[n][2] + ac_hl[n][2] + ac_lh[n][2];
                Gs[(r + 8) * 132 + col + 1] = ac_hh[n][3] + ac_hl[n][3] + ac_lh[n][3];
            }
            __syncthreads();
        }

        float gA[4] = {0.f,0.f,0.f,0.f}, gB[4] = {0.f,0.f,0.f,0.f};
        if (s > 0) {
            *(float4*)gA = *(const float4*)&Gs[bl * 132 + jlA * 4];
            *(float4*)gB = *(const float4*)&Gs[bl * 132 + (jlA + 16) * 4];
        }
        float* hrow = g_bl + ((size_t)(t * 256 + b0 + bl)) * 256 + (dir << 7) + j0;
        {
            float iv = fast_sig(gA[0] + xa[0]), fv = fast_sig(gA[1] + xa[1]);
            float gv = fast_tanh(gA[2] + xa[2]), ov = fast_sig(gA[3] + xa[3]);
            cA = fv * cA + iv * gv;
            hrow[jlA] = ov * fast_tanh(cA);
        }
        {
            float iv = fast_sig(gB[0] + xb[0]), fv = fast_sig(gB[1] + xb[1]);
            float gv = fast_tanh(gB[2] + xb[2]), ov = fast_sig(gB[3] + xb[3]);
            cB = fv * cB + iv * gv;
            hrow[jlA + 16] = ov * fast_tanh(cB);
        }
        __syncthreads();
        if (tid == 0) flag_release(fb + s * 4 + jj);
    }
}

// ---------------- H2=256 persistent scan (layers 1,2), grid (8,16) -------------
template<int LAYER>
__global__ void __launch_bounds__(256) scan256_kernel(const float* __restrict__ Whh)
{
    const int bi = blockIdx.x;
    const int jj = blockIdx.y;
    const int tid = threadIdx.x, lane = tid & 31, w = tid >> 5;
    const int j0 = jj * 16, b0 = bi * 32;

    extern __shared__ unsigned smu[];
    unsigned* Wh = smu;                    // 64 rows x 128 words
    unsigned* Wl = Wh + 8192;
    unsigned* Hh = Wl + 8192;              // 32 rows x 128 words
    unsigned* Hl = Hh + 4096;
    float*    Gs = (float*)(Hl + 4096);    // [32][68]

    float* hbuf = (LAYER == 1) ? g_h1 : g_h2;
    int* fb = g_flags + 32768 + (LAYER - 1) * 32768 + bi * 4096;  // [256][16]

#pragma unroll
    for (int i = 0; i < 16; i++) {
        int v = tid + i * 256;
        int r = v >> 6, k4 = v & 63;
        int jl = r >> 2, g = r & 3;
        float4 wv = *(const float4*)(Whh + (size_t)(g * 256 + j0 + jl) * 256 + k4 * 4);
        int wo = r * 128 + (((k4 * 2) ^ ((r & 7) << 2)));
        unsigned h0, l0, h1, l1;
        split2(wv.x, wv.y, h0, l0);
        split2(wv.z, wv.w, h1, l1);
        *(uint2*)&Wh[wo] = make_uint2(h0, h1);
        *(uint2*)&Wl[wo] = make_uint2(l0, l1);
    }
    __syncthreads();

    const int m0 = (w & 1) * 16;
    const int nt0 = (w >> 1) * 2;
    const int bl = tid >> 4;
    const int jl = tid & 15;
    float cA = 0.f, cB = 0.f;

    for (int s = 0; s < 256; s++) {
        const int t = s;

        float xa[4], xb[4];
        {
            const float* xrA = g_xg1 + ((size_t)(t * 256 + b0 + bl)) * 1024 + j0 + jl;
            const float* xrB = g_xg1 + ((size_t)(t * 256 + b0 + bl + 16)) * 1024 + j0 + jl;
#pragma unroll
            for (int g = 0; g < 4; g++) { xa[g] = xrA[g << 8]; xb[g] = xrB[g << 8]; }
        }

        if (s > 0) {
            if (w == 0) spin_wait<16>(fb + (s - 1) * 16, lane);
            __syncthreads();
#pragma unroll
            for (int i = 0; i < 8; i++) {
                int v = tid + i * 256;
                int r = v >> 6, k4 = v & 63;
                float4 hv = *(const float4*)(hbuf + ((size_t)((t - 1) * 256 + b0 + r)) * 256 + k4 * 4);
                int wo = r * 128 + (((k4 * 2) ^ ((r & 7) << 2)));
                unsigned h0, l0, h1, l1;
                split2(hv.x, hv.y, h0, l0);
                split2(hv.z, hv.w, h1, l1);
                *(uint2*)&Hh[wo] = make_uint2(h0, h1);
                *(uint2*)&Hl[wo] = make_uint2(l0, l1);
            }
            __syncthreads();

            float ac_hh[2][4] = {{0,0,0,0},{0,0,0,0}};
            float ac_hl[2][4] = {{0,0,0,0},{0,0,0,0}};
            float ac_lh[2][4] = {{0,0,0,0},{0,0,0,0}};
            unsigned fA[2][8], fB[2][8];
            auto loadf = [&](int ks, int buf) {
                const int kw = ks * 8 + (lane & 3);
                const int ra = m0 + (lane >> 2);
                fA[buf][0] = Hh[OW1(ra, kw)];     fA[buf][1] = Hh[OW1(ra + 8, kw)];
                fA[buf][2] = Hh[OW1(ra, kw + 4)]; fA[buf][3] = Hh[OW1(ra + 8, kw + 4)];
                fA[buf][4] = Hl[OW1(ra, kw)];     fA[buf][5] = Hl[OW1(ra + 8, kw)];
                fA[buf][6] = Hl[OW1(ra, kw + 4)]; fA[buf][7] = Hl[OW1(ra + 8, kw + 4)];
                const int nr0 = nt0 * 8 + (lane >> 2), nr1 = (nt0 + 1) * 8 + (lane >> 2);
                fB[buf][0] = Wh[OW1(nr0, kw)]; fB[buf][1] = Wh[OW1(nr0, kw + 4)];
                fB[buf][2] = Wl[OW1(nr0, kw)]; fB[buf][3] = Wl[OW1(nr0, kw + 4)];
                fB[buf][4] = Wh[OW1(nr1, kw)]; fB[buf][5] = Wh[OW1(nr1, kw + 4)];
                fB[buf][6] = Wl[OW1(nr1, kw)]; fB[buf][7] = Wl[OW1(nr1, kw + 4)];
            };
            loadf(0, 0);
#pragma unroll
            for (int ks = 0; ks < 16; ks++) {
                const int cb = ks & 1;
                if (ks < 15) loadf(ks + 1, cb ^ 1);
                const unsigned* A = fA[cb];
                const unsigned* B = fB[cb];
                mma_bf16(ac_hh[0], A,     B);
                mma_bf16(ac_hl[0], A,     B + 2);
                mma_bf16(ac_lh[0], A + 4, B);
                mma_bf16(ac_hh[1], A,     B + 4);
                mma_bf16(ac_hl[1], A,     B + 6);
                mma_bf16(ac_lh[1], A + 4, B + 4);
            }
#pragma unroll
            for (int n = 0; n < 2; n++) {
                int col = (nt0 + n) * 8 + 2 * (lane & 3);
                int r = m0 + (lane >> 2);
                Gs[r * 68 + col]           = ac_hh[n][0] + ac_hl[n][0] + ac_lh[n][0];
                Gs[r * 68 + col + 1]       = ac_hh[n][1] + ac_hl[n][1] + ac_lh[n][1];
                Gs[(r + 8) * 68 + col]     = ac_hh[n][2] + ac_hl[n][2] + ac_lh[n][2];
                Gs[(r + 8) * 68 + col + 1] = ac_hh[n][3] + ac_hl[n][3] + ac_lh[n][3];
            }
            __syncthreads();
        }

        float gA[4] = {0.f,0.f,0.f,0.f}, gB[4] = {0.f,0.f,0.f,0.f};
        if (s > 0) {
            *(float4*)gA = *(const float4*)&Gs[bl * 68 + jl * 4];
            *(float4*)gB = *(const float4*)&Gs[(bl + 16) * 68 + jl * 4];
        }
        {
            float iv = fast_sig(gA[0] + xa[0]), fv = fast_sig(gA[1] + xa[1]);
            float gv = fast_tanh(gA[2] + xa[2]), ov = fast_sig(gA[3] + xa[3]);
            cA = fv * cA + iv * gv;
            hbuf[((size_t)(t * 256 + b0 + bl)) * 256 + j0 + jl] = ov * fast_tanh(cA);
        }
        {
            float iv = fast_sig(gB[0] + xb[0]), fv = fast_sig(gB[1] + xb[1]);
            float gv = fast_tanh(gB[2] + xb[2]), ov = fast_sig(gB[3] + xb[3]);
            cB = fv * cB + iv * gv;
            hbuf[((size_t)(t * 256 + b0 + bl + 16)) * 256 + j0 + jl] = ov * fast_tanh(cB);
        }
        __syncthreads();
        if (tid == 0) flag_release(fb + s * 16 + jj);
    }
}

// ---------------- LayerNorm over last dim (256), warp per row ----------------
template<int WHICH>
__global__ void __launch_bounds__(256) ln_kernel(const float* __restrict__ gam,
                                                 const float* __restrict__ bet)
{
    const int warp = threadIdx.x >> 5, lane = threadIdx.x & 31;
    const size_t row = (size_t)blockIdx.x * 8 + warp;
    const float* x = (WHICH == 1) ? g_bl : g_h1;
    float* out = (WHICH == 1) ? g_bl : g_h1;
    const size_t base = row * 256 + lane * 8;

    float4 a0 = *(const float4*)(x + base);
    float4 a1 = *(const float4*)(x + base + 4);
    if (WHICH == 2) {
        float4 r0 = *(const float4*)(g_bl + base);
        float4 r1 = *(const float4*)(g_bl + base + 4);
        a0.x += r0.x; a0.y += r0.y; a0.z += r0.z; a0.w += r0.w;
        a1.x += r1.x; a1.y += r1.y; a1.z += r1.z; a1.w += r1.w;
    }
    float v[8] = {a0.x,a0.y,a0.z,a0.w,a1.x,a1.y,a1.z,a1.w};
    float s = 0.f;
#pragma unroll
    for (int i = 0; i < 8; i++) s += v[i];
#pragma unroll
    for (int o = 16; o; o >>= 1) s += __shfl_xor_sync(0xffffffffu, s, o);
    float mu = s * (1.f / 256.f);
    float ss = 0.f;
#pragma unroll
    for (int i = 0; i < 8; i++) { v[i] -= mu; ss += v[i] * v[i]; }
#pragma unroll
    for (int o = 16; o; o >>= 1) ss += __shfl_xor_sync(0xffffffffu, ss, o);
    float rs = rsqrtf(ss * (1.f / 256.f) + 1e-5f);
    const int c0 = lane * 8;
    float4 g0 = *(const float4*)(gam + c0), g1 = *(const float4*)(gam + c0 + 4);
    float4 b0 = *(const float4*)(bet + c0), b1 = *(const float4*)(bet + c0 + 4);
    float gg[8] = {g0.x,g0.y,g0.z,g0.w,g1.x,g1.y,g1.z,g1.w};
    float bb[8] = {b0.x,b0.y,b0.z,b0.w,b1.x,b1.y,b1.z,b1.w};
    float4 o0, o1;
    o0.x = v[0]*rs*gg[0]+bb[0]; o0.y = v[1]*rs*gg[1]+bb[1];
    o0.z = v[2]*rs*gg[2]+bb[2]; o0.w = v[3]*rs*gg[3]+bb[3];
    o1.x = v[4]*rs*gg[4]+bb[4]; o1.y = v[5]*rs*gg[5]+bb[5];
    o1.z = v[6]*rs*gg[6]+bb[6]; o1.w = v[7]*rs*gg[7]+bb[7];
    *(float4*)(out + base) = o0;
    *(float4*)(out + base + 4) = o1;
}

// ---------------- gather + affine + relu (auto int32/int64 idx) ----------------
__global__ void __launch_bounds__(256) gather_kernel(const int* __restrict__ idx32,
                                                     const float* __restrict__ bn_g,
                                                     const float* __restrict__ bn_b,
                                                     float* __restrict__ out)
{
    __shared__ int sidx;
    const int b = blockIdx.x, j = threadIdx.x;
    if (j < 32) {
        int v = idx32[2 * j + 1];
        unsigned m = __ballot_sync(0xffffffffu, v != 0);
        if (j == 0) sidx = (m == 0) ? idx32[2 * b] : idx32[b];
    }
    __syncthreads();
    const int t = sidx;
    float scale = rsqrtf(1.0f + 1e-5f);
    float y = g_h2[((size_t)(t * 256 + b)) * 256 + j] * scale * bn_g[j] + bn_b[j];
    out[(size_t)b * 256 + j] = fmaxf(y, 0.f);
}

// ---------------- launch ----------------
extern "C" void kernel_launch(void* const* d_in, const int* in_sizes, int n_in,
                              void* d_out, int out_size)
{
    const float* inp   = (const float*)d_in[0];
    const int*   idx   = (const int*)  d_in[1];
    const float* Wih_f = (const float*)d_in[2];
    const float* Whh_f = (const float*)d_in[3];
    const float* b_f   = (const float*)d_in[4];
    const float* Wih_r = (const float*)d_in[5];
    const float* Whh_r = (const float*)d_in[6];
    const float* b_r   = (const float*)d_in[7];
    const float* ln1_g = (const float*)d_in[8];
    const float* ln1_b = (const float*)d_in[9];
    const float* W1ih  = (const float*)d_in[10];
    const float* W1hh  = (const float*)d_in[11];
    const float* b1    = (const float*)d_in[12];
    const float* ln2_g = (const float*)d_in[13];
    const float* ln2_b = (const float*)d_in[14];
    const float* W2ih  = (const float*)d_in[15];
    const float* W2hh  = (const float*)d_in[16];
    const float* b2    = (const float*)d_in[17];
    const float* bn_g  = (const float*)d_in[18];
    const float* bn_b  = (const float*)d_in[19];
    float* out = (float*)d_out;

    const int SMG = 16384 * 4;                                   // 64 KB gemm
    const int SM0 = (8192 * 2 + 1024 * 2) * 4 + 16 * 132 * 4;    // 82176
    const int SM1 = (8192 * 2 + 4096 * 2) * 4 + 32 * 68 * 4;     // 107008
    cudaFuncSetAttribute(mma_gemm<128, 512, 0>, cudaFuncAttributeMaxDynamicSharedMemorySize, SMG);
    cudaFuncSetAttribute(mma_gemm<128, 512, 1>, cudaFuncAttributeMaxDynamicSharedMemorySize, SMG);
    cudaFuncSetAttribute(mma_gemm<256, 1024, 2>, cudaFuncAttributeMaxDynamicSharedMemorySize, SMG);
    cudaFuncSetAttribute(mma_gemm<256, 1024, 3>, cudaFuncAttributeMaxDynamicSharedMemorySize, SMG);
    cudaFuncSetAttribute(scan0_kernel,      cudaFuncAttributeMaxDynamicSharedMemorySize, SM0);
    cudaFuncSetAttribute(scan256_kernel<1>, cudaFuncAttributeMaxDynamicSharedMemorySize, SM1);
    cudaFuncSetAttribute(scan256_kernel<2>, cudaFuncAttributeMaxDynamicSharedMemorySize, SM1);

    zero_flags_kernel<<<512, 256>>>();
    mma_gemm<128, 512, 0><<<dim3(512, 4), 256, SMG>>>(inp, Wih_f, b_f);
    mma_gemm<128, 512, 1><<<dim3(512, 4), 256, SMG>>>(inp, Wih_r, b_r);
    scan0_kernel<<<dim3(16, 4, 2), 256, SM0>>>(Whh_f, Whh_r);
    ln_kernel<1><<<8192, 256>>>(ln1_g, ln1_b);
    mma_gemm<256, 1024, 2><<<dim3(512, 8), 256, SMG>>>(nullptr, W1ih, b1);
    scan256_kernel<1><<<dim3(8, 16), 256, SM1>>>(W1hh);
    ln_kernel<2><<<8192, 256>>>(ln2_g, ln2_b);
    mma_gemm<256, 1024, 3><<<dim3(512, 8), 256, SMG>>>(nullptr, W2ih, b2);
    scan256_kernel<2><<<dim3(8, 16), 256, SM1>>>(W2hh);
    gather_kernel<<<256, 256>>>(idx, bn_g, bn_b, out);
}

// round 17
// speedup vs baseline: 1.0437x; 1.0437x over previous
#include <cuda_runtime.h>
#include <cuda_bf16.h>
#include <math.h>

#define TT 256
#define BSZ 256

// ---------------- device scratch (no allocation APIs) ----------------
static __device__ float g_xg0f[33554432];   // [T*B][512]
static __device__ float g_xg0r[33554432];   // [T*B][512]
static __device__ float g_xg1 [67108864];   // [T*B][1024] (layer1, reused layer2)
static __device__ float g_bl  [16777216];   // [T*B][256]  bilstm h -> LN1 in place
static __device__ float g_h1  [16777216];   // [T*B][256]  layer1 h -> LN2 in place
static __device__ float g_h2  [16777216];   // [T*B][256]  layer2 h
static __device__ int   g_flags[131072];    // per-CTA step flags
// producer-split bf16 h planes (hi/lo packed as bf16 pairs per 32-bit word)
static __device__ unsigned g_bsp_h[8388608];  // scan0: [2 dir][T*B][64 words]
static __device__ unsigned g_bsp_l[8388608];
static __device__ unsigned g_hsp_h[8388608];  // scan256 (reused L1/L2): [T*B][128 words]
static __device__ unsigned g_hsp_l[8388608];

__global__ void zero_flags_kernel() {
    int i = blockIdx.x * blockDim.x + threadIdx.x;
    if (i < 131072) g_flags[i] = 0;
}

// ---------------- tf32 helpers (input-projection GEMMs) ----------------
__device__ __forceinline__ unsigned f2tf32(float x) {
    unsigned r;
    asm("cvt.rna.tf32.f32 %0, %1;" : "=r"(r) : "f"(x));
    return r;
}
__device__ __forceinline__ void mma_tf32(float c[4], const unsigned a[4], const unsigned b[2]) {
    asm volatile(
        "mma.sync.aligned.m16n8k8.row.col.f32.tf32.tf32.f32 "
        "{%0,%1,%2,%3}, {%4,%5,%6,%7}, {%8,%9}, {%0,%1,%2,%3};"
        : "+f"(c[0]), "+f"(c[1]), "+f"(c[2]), "+f"(c[3])
        : "r"(a[0]), "r"(a[1]), "r"(a[2]), "r"(a[3]), "r"(b[0]), "r"(b[1]));
}

// ---------------- bf16 helpers (recurrent scans) ----------------
__device__ __forceinline__ void mma_bf16(float c[4], const unsigned* a, const unsigned* b) {
    asm volatile(
        "mma.sync.aligned.m16n8k16.row.col.f32.bf16.bf16.f32 "
        "{%0,%1,%2,%3}, {%4,%5,%6,%7}, {%8,%9}, {%0,%1,%2,%3};"
        : "+f"(c[0]), "+f"(c[1]), "+f"(c[2]), "+f"(c[3])
        : "r"(a[0]), "r"(a[1]), "r"(a[2]), "r"(a[3]), "r"(b[0]), "r"(b[1]));
}
__device__ __forceinline__ void split2(float a, float b, unsigned& hi, unsigned& lo) {
    __nv_bfloat162 h = __floats2bfloat162_rn(a, b);
    float2 hf = __bfloat1622float2(h);
    __nv_bfloat162 l = __floats2bfloat162_rn(a - hf.x, b - hf.y);
    hi = *(unsigned*)&h;
    lo = *(unsigned*)&l;
}
// producer-side: store hi/lo bf16 halves of v into the half-th b16 slot of word
__device__ __forceinline__ void store_split(unsigned* baseH, unsigned* baseL,
                                            size_t word, int half, float v) {
    __nv_bfloat16 hb = __float2bfloat16(v);
    float hf = __bfloat162float(hb);
    __nv_bfloat16 lb = __float2bfloat16(v - hf);
    ((unsigned short*)(baseH + word))[half] = *(unsigned short*)&hb;
    ((unsigned short*)(baseL + word))[half] = *(unsigned short*)&lb;
}

// XOR-swizzled word offsets: row strides 64/128/32, all ≡0 mod 32
#define OW0(r, w) ((r) * 64  + ((w) ^ ((((r) & 7)) << 2)))
#define OW1(r, w) ((r) * 128 + ((w) ^ ((((r) & 7)) << 2)))
#define OWG(r, k) ((r) * 32 + (((((k) >> 2) ^ ((r) & 7))) << 2) + ((k) & 3))

// ---------------- fast transcendentals ----------------
__device__ __forceinline__ float fast_sig(float x) {
    return __fdividef(1.f, 1.f + __expf(-x));
}
__device__ __forceinline__ float fast_tanh(float x) {
    float t = __expf(-2.f * fabsf(x));
    float r = __fdividef(1.f - t, 1.f + t);
    return copysignf(r, x);
}

// ---------------- handshake primitives ----------------
__device__ __forceinline__ void flag_release(int* p) {
    asm volatile("st.release.gpu.s32 [%0], %1;" :: "l"(p), "r"(1) : "memory");
}
__device__ __forceinline__ int flag_acquire(const int* p) {
    int v;
    asm volatile("ld.acquire.gpu.s32 %0, [%1];" : "=r"(v) : "l"(p));
    return v;
}
template<int NC>
__device__ __forceinline__ void spin_wait(const int* fp, int lane) {
    int done = 0;
    do {
        int v = 1;
        if (lane < NC) v = flag_acquire(fp + lane);
        done = __all_sync(0xffffffffu, v != 0);
    } while (!done);
}

// ---------------- cp.async helpers ----------------
__device__ __forceinline__ void cp16(void* dst_smem, const void* src) {
    unsigned d = (unsigned)__cvta_generic_to_shared(dst_smem);
    asm volatile("cp.async.cg.shared.global [%0], [%1], 16;" :: "r"(d), "l"(src));
}
#define CP_COMMIT() asm volatile("cp.async.commit_group;")
#define CP_WAIT(n)  asm volatile("cp.async.wait_group %0;" :: "n"(n))

// ---------------- tf32 GEMM, cp.async 2-stage double buffer (R14, measured) ---
template<int K, int N, int MODE>
__global__ void __launch_bounds__(256) mma_gemm(const float* __restrict__ Ap,
                                                const float* __restrict__ W,
                                                const float* __restrict__ bias)
{
    extern __shared__ float smg[];
    float* AsF = smg;            // [2][4096]
    float* BsF = smg + 8192;     // [2][4096]

    const int tid = threadIdx.x, lane = tid & 31, wid = tid >> 5;
    const int warpM = wid >> 1, warpN = wid & 1;
    const int cRow = blockIdx.x, cCol = blockIdx.y;

    float acc[2][8][4];
#pragma unroll
    for (int mt = 0; mt < 2; mt++)
#pragma unroll
        for (int nt = 0; nt < 8; nt++)
#pragma unroll
            for (int i = 0; i < 4; i++) acc[mt][nt][i] = 0.f;

    auto stage = [&](int kt, int bf) {
#pragma unroll
        for (int i = 0; i < 4; i++) {
            int f = tid + i * 256;
            int row = f >> 3, c = f & 7;
            const float* ap;
            if (MODE <= 1) {
                int m = cRow * 128 + row;
                ap = Ap + ((size_t)(m & 255) * TT + (m >> 8)) * 128 + kt + c * 4;
            } else if (MODE == 2) {
                ap = g_bl + (size_t)(cRow * 128 + row) * K + kt + c * 4;
            } else {
                ap = g_h1 + (size_t)(cRow * 128 + row) * K + kt + c * 4;
            }
            const float* bp = W + (size_t)(cCol * 128 + row) * K + kt + c * 4;
            int wo = row * 32 + ((c ^ (row & 7)) << 2);
            cp16(&AsF[bf * 4096 + wo], ap);
            cp16(&BsF[bf * 4096 + wo], bp);
        }
        CP_COMMIT();
    };

    stage(0, 0);
    int bf = 0;
    for (int kt = 0; kt < K; kt += 32) {
        if (kt + 32 < K) { stage(kt + 32, bf ^ 1); CP_WAIT(1); }
        else             { CP_WAIT(0); }
        __syncthreads();

        const float* Ab = &AsF[bf * 4096];
        const float* Bb = &BsF[bf * 4096];
#pragma unroll
        for (int kk = 0; kk < 32; kk += 8) {
            const int k0 = kk + (lane & 3);
            unsigned a[2][4], b[8][2];
#pragma unroll
            for (int mt = 0; mt < 2; mt++) {
                int row = warpM * 32 + mt * 16 + (lane >> 2);
                a[mt][0] = f2tf32(Ab[OWG(row, k0)]);
                a[mt][1] = f2tf32(Ab[OWG(row + 8, k0)]);
                a[mt][2] = f2tf32(Ab[OWG(row, k0 + 4)]);
                a[mt][3] = f2tf32(Ab[OWG(row + 8, k0 + 4)]);
            }
#pragma unroll
            for (int nt = 0; nt < 8; nt++) {
                int col = warpN * 64 + nt * 8 + (lane >> 2);
                b[nt][0] = f2tf32(Bb[OWG(col, k0)]);
                b[nt][1] = f2tf32(Bb[OWG(col, k0 + 4)]);
            }
#pragma unroll
            for (int mt = 0; mt < 2; mt++)
#pragma unroll
                for (int nt = 0; nt < 8; nt++)
                    mma_tf32(acc[mt][nt], a[mt], b[nt]);
        }
        __syncthreads();
        bf ^= 1;
    }

    float* Cout = (MODE == 0) ? g_xg0f : (MODE == 1) ? g_xg0r : g_xg1;
#pragma unroll
    for (int nt = 0; nt < 8; nt++) {
        int c = cCol * 128 + warpN * 64 + nt * 8 + (lane & 3) * 2;
        float bx = bias[c], by = bias[c + 1];
#pragma unroll
        for (int mt = 0; mt < 2; mt++) {
            int r0 = cRow * 128 + warpM * 32 + mt * 16 + (lane >> 2);
            float2 o0 = {acc[mt][nt][0] + bx, acc[mt][nt][1] + by};
            float2 o1 = {acc[mt][nt][2] + bx, acc[mt][nt][3] + by};
            *(float2*)(Cout + (size_t)r0 * N + c)       = o0;
            *(float2*)(Cout + (size_t)(r0 + 8) * N + c) = o1;
        }
    }
}

// ---------------- layer0 persistent scan, H=128, grid (16,4,2) ----------------
// Producer-split transport: consumers cp.async the pre-split bf16 planes.
__global__ void __launch_bounds__(256) scan0_kernel(const float* __restrict__ WhhF,
                                                    const float* __restrict__ WhhR)
{
    const int bi = blockIdx.x, jj = blockIdx.y, dir = blockIdx.z;
    const int tid = threadIdx.x, lane = tid & 31, w = tid >> 5;
    const int j0 = jj * 32, b0 = bi * 16;

    extern __shared__ unsigned smu[];
    unsigned* Wh = smu;                    // 128 rows x 64 words
    unsigned* Wl = Wh + 8192;
    unsigned* Hh = Wl + 8192;              // 16 rows x 64 words
    unsigned* Hl = Hh + 1024;
    float*    Gs = (float*)(Hl + 1024);    // [16][132]

    const float* Whh = dir ? WhhR : WhhF;
    const float* xg  = dir ? g_xg0r : g_xg0f;
    int* fb = g_flags + (dir * 16 + bi) * 1024;   // [256 steps][4 CTAs]
    unsigned* sp_h = g_bsp_h + (size_t)dir * 4194304;   // [T*B][64 words]
    unsigned* sp_l = g_bsp_l + (size_t)dir * 4194304;

#pragma unroll
    for (int i = 0; i < 16; i++) {
        int v = tid + i * 256;
        int r = v >> 5, k4 = v & 31;
        int jl = r >> 2, g = r & 3;
        float4 wv = *(const float4*)(Whh + (size_t)(g * 128 + j0 + jl) * 128 + k4 * 4);
        int wo = r * 64 + (((k4 * 2) ^ ((r & 7) << 2)));
        unsigned h0, l0, h1, l1;
        split2(wv.x, wv.y, h0, l0);
        split2(wv.z, wv.w, h1, l1);
        *(uint2*)&Wh[wo] = make_uint2(h0, h1);
        *(uint2*)&Wl[wo] = make_uint2(l0, l1);
    }
    __syncthreads();

    const int nt0 = w * 2;
    const int bl = tid >> 4;
    const int jlA = tid & 15;
    float cA = 0.f, cB = 0.f;

    for (int s = 0; s < 256; s++) {
        const int t = dir ? (255 - s) : s;

        float xa[4], xb[4];
        {
            const float* xr = xg + ((size_t)(t * 256 + b0 + bl)) * 512 + j0;
#pragma unroll
            for (int g = 0; g < 4; g++) { xa[g] = xr[(g << 7) + jlA]; xb[g] = xr[(g << 7) + jlA + 16]; }
        }

        if (s > 0) {
            const int tp = dir ? (t + 1) : (t - 1);
            if (w == 0) spin_wait<4>(fb + (s - 1) * 4, lane);
            __syncthreads();
            // cp.async the pre-split h planes straight into swizzled SMEM
            {
                int r = tid >> 4, c4 = tid & 15;     // 16 rows x 16 chunks
                size_t src = (size_t)(tp * 256 + b0 + r) * 64 + c4 * 4;
                int dst = r * 64 + ((c4 * 4) ^ ((r & 7) << 2));
                cp16(&Hh[dst], sp_h + src);
                cp16(&Hl[dst], sp_l + src);
            }
            CP_COMMIT();
            CP_WAIT(0);
            __syncthreads();

            float acc[2][4] = {{0.f,0.f,0.f,0.f},{0.f,0.f,0.f,0.f}};
            unsigned fA[2][8], fB[2][8];
            auto loadf = [&](int ks, int buf) {
                const int kw = ks * 8 + (lane & 3);
                const int ra = lane >> 2;
                fA[buf][0] = Hh[OW0(ra, kw)];     fA[buf][1] = Hh[OW0(ra + 8, kw)];
                fA[buf][2] = Hh[OW0(ra, kw + 4)]; fA[buf][3] = Hh[OW0(ra + 8, kw + 4)];
                fA[buf][4] = Hl[OW0(ra, kw)];     fA[buf][5] = Hl[OW0(ra + 8, kw)];
                fA[buf][6] = Hl[OW0(ra, kw + 4)]; fA[buf][7] = Hl[OW0(ra + 8, kw + 4)];
                const int nr0 = nt0 * 8 + (lane >> 2), nr1 = (nt0 + 1) * 8 + (lane >> 2);
                fB[buf][0] = Wh[OW0(nr0, kw)]; fB[buf][1] = Wh[OW0(nr0, kw + 4)];
                fB[buf][2] = Wl[OW0(nr0, kw)]; fB[buf][3] = Wl[OW0(nr0, kw + 4)];
                fB[buf][4] = Wh[OW0(nr1, kw)]; fB[buf][5] = Wh[OW0(nr1, kw + 4)];
                fB[buf][6] = Wl[OW0(nr1, kw)]; fB[buf][7] = Wl[OW0(nr1, kw + 4)];
            };
            loadf(0, 0);
#pragma unroll
            for (int ks = 0; ks < 8; ks++) {
                const int cb = ks & 1;
                if (ks < 7) loadf(ks + 1, cb ^ 1);
                const unsigned* A = fA[cb];
                const unsigned* B = fB[cb];
                mma_bf16(acc[0], A,     B);
                mma_bf16(acc[0], A,     B + 2);
                mma_bf16(acc[0], A + 4, B);
                mma_bf16(acc[1], A,     B + 4);
                mma_bf16(acc[1], A,     B + 6);
                mma_bf16(acc[1], A + 4, B + 4);
            }
#pragma unroll
            for (int n = 0; n < 2; n++) {
                int col = (nt0 + n) * 8 + 2 * (lane & 3);
                int r = lane >> 2;
                Gs[r * 132 + col]           = acc[n][0];
                Gs[r * 132 + col + 1]       = acc[n][1];
                Gs[(r + 8) * 132 + col]     = acc[n][2];
                Gs[(r + 8) * 132 + col + 1] = acc[n][3];
            }
            __syncthreads();
        }

        float gA[4] = {0.f,0.f,0.f,0.f}, gB[4] = {0.f,0.f,0.f,0.f};
        if (s > 0) {
            *(float4*)gA = *(const float4*)&Gs[bl * 132 + jlA * 4];
            *(float4*)gB = *(const float4*)&Gs[bl * 132 + (jlA + 16) * 4];
        }
        float* hrow = g_bl + ((size_t)(t * 256 + b0 + bl)) * 256 + (dir << 7) + j0;
        const size_t sprow = (size_t)(t * 256 + b0 + bl) * 64;
        const int wA = (j0 + jlA) >> 1, half = jlA & 1;
        {
            float iv = fast_sig(gA[0] + xa[0]), fv = fast_sig(gA[1] + xa[1]);
            float gv = fast_tanh(gA[2] + xa[2]), ov = fast_sig(gA[3] + xa[3]);
            cA = fv * cA + iv * gv;
            float hv = ov * fast_tanh(cA);
            hrow[jlA] = hv;
            store_split(sp_h, sp_l, sprow + wA, half, hv);
        }
        {
            float iv = fast_sig(gB[0] + xb[0]), fv = fast_sig(gB[1] + xb[1]);
            float gv = fast_tanh(gB[2] + xb[2]), ov = fast_sig(gB[3] + xb[3]);
            cB = fv * cB + iv * gv;
            float hv = ov * fast_tanh(cB);
            hrow[jlA + 16] = hv;
            store_split(sp_h, sp_l, sprow + wA + 8, half, hv);
        }
        __syncthreads();
        if (tid == 0) flag_release(fb + s * 4 + jj);
    }
}

// ---------------- H2=256 persistent scan (layers 1,2), grid (8,16) -------------
template<int LAYER>
__global__ void __launch_bounds__(256) scan256_kernel(const float* __restrict__ Whh)
{
    const int bi = blockIdx.x;
    const int jj = blockIdx.y;
    const int tid = threadIdx.x, lane = tid & 31, w = tid >> 5;
    const int j0 = jj * 16, b0 = bi * 32;

    extern __shared__ unsigned smu[];
    unsigned* Wh = smu;                    // 64 rows x 128 words
    unsigned* Wl = Wh + 8192;
    unsigned* Hh = Wl + 8192;              // 32 rows x 128 words
    unsigned* Hl = Hh + 4096;
    float*    Gs = (float*)(Hl + 4096);    // [32][68]

    float* hbuf = (LAYER == 1) ? g_h1 : g_h2;
    int* fb = g_flags + 32768 + (LAYER - 1) * 32768 + bi * 4096;  // [256][16]

#pragma unroll
    for (int i = 0; i < 16; i++) {
        int v = tid + i * 256;
        int r = v >> 6, k4 = v & 63;
        int jl = r >> 2, g = r & 3;
        float4 wv = *(const float4*)(Whh + (size_t)(g * 256 + j0 + jl) * 256 + k4 * 4);
        int wo = r * 128 + (((k4 * 2) ^ ((r & 7) << 2)));
        unsigned h0, l0, h1, l1;
        split2(wv.x, wv.y, h0, l0);
        split2(wv.z, wv.w, h1, l1);
        *(uint2*)&Wh[wo] = make_uint2(h0, h1);
        *(uint2*)&Wl[wo] = make_uint2(l0, l1);
    }
    __syncthreads();

    const int m0 = (w & 1) * 16;
    const int nt0 = (w >> 1) * 2;
    const int bl = tid >> 4;
    const int jl = tid & 15;
    float cA = 0.f, cB = 0.f;

    for (int s = 0; s < 256; s++) {
        const int t = s;

        float xa[4], xb[4];
        {
            const float* xrA = g_xg1 + ((size_t)(t * 256 + b0 + bl)) * 1024 + j0 + jl;
            const float* xrB = g_xg1 + ((size_t)(t * 256 + b0 + bl + 16)) * 1024 + j0 + jl;
#pragma unroll
            for (int g = 0; g < 4; g++) { xa[g] = xrA[g << 8]; xb[g] = xrB[g << 8]; }
        }

        if (s > 0) {
            if (w == 0) spin_wait<16>(fb + (s - 1) * 16, lane);
            __syncthreads();
            // cp.async the pre-split h planes (32 rows x 32 chunks per plane)
#pragma unroll
            for (int i = 0; i < 4; i++) {
                int v = tid + i * 256;
                int r = v >> 5, c4 = v & 31;
                size_t src = (size_t)((t - 1) * 256 + b0 + r) * 128 + c4 * 4;
                int dst = r * 128 + ((c4 * 4) ^ ((r & 7) << 2));
                cp16(&Hh[dst], g_hsp_h + src);
                cp16(&Hl[dst], g_hsp_l + src);
            }
            CP_COMMIT();
            CP_WAIT(0);
            __syncthreads();

            float acc[2][4] = {{0.f,0.f,0.f,0.f},{0.f,0.f,0.f,0.f}};
            unsigned fA[2][8], fB[2][8];
            auto loadf = [&](int ks, int buf) {
                const int kw = ks * 8 + (lane & 3);
                const int ra = m0 + (lane >> 2);
                fA[buf][0] = Hh[OW1(ra, kw)];     fA[buf][1] = Hh[OW1(ra + 8, kw)];
                fA[buf][2] = Hh[OW1(ra, kw + 4)]; fA[buf][3] = Hh[OW1(ra + 8, kw + 4)];
                fA[buf][4] = Hl[OW1(ra, kw)];     fA[buf][5] = Hl[OW1(ra + 8, kw)];
                fA[buf][6] = Hl[OW1(ra, kw + 4)]; fA[buf][7] = Hl[OW1(ra + 8, kw + 4)];
                const int nr0 = nt0 * 8 + (lane >> 2), nr1 = (nt0 + 1) * 8 + (lane >> 2);
                fB[buf][0] = Wh[OW1(nr0, kw)]; fB[buf][1] = Wh[OW1(nr0, kw + 4)];
                fB[buf][2] = Wl[OW1(nr0, kw)]; fB[buf][3] = Wl[OW1(nr0, kw + 4)];
                fB[buf][4] = Wh[OW1(nr1, kw)]; fB[buf][5] = Wh[OW1(nr1, kw + 4)];
                fB[buf][6] = Wl[OW1(nr1, kw)]; fB[buf][7] = Wl[OW1(nr1, kw + 4)];
            };
            loadf(0, 0);
#pragma unroll
            for (int ks = 0; ks < 16; ks++) {
                const int cb = ks & 1;
                if (ks < 15) loadf(ks + 1, cb ^ 1);
                const unsigned* A = fA[cb];
                const unsigned* B = fB[cb];
                mma_bf16(acc[0], A,     B);
                mma_bf16(acc[0], A,     B + 2);
                mma_bf16(acc[0], A + 4, B);
                mma_bf16(acc[1], A,     B + 4);
                mma_bf16(acc[1], A,     B + 6);
                mma_bf16(acc[1], A + 4, B + 4);
            }
#pragma unroll
            for (int n = 0; n < 2; n++) {
                int col = (nt0 + n) * 8 + 2 * (lane & 3);
                int r = m0 + (lane >> 2);
                Gs[r * 68 + col]           = acc[n][0];
                Gs[r * 68 + col + 1]       = acc[n][1];
                Gs[(r + 8) * 68 + col]     = acc[n][2];
                Gs[(r + 8) * 68 + col + 1] = acc[n][3];
            }
            __syncthreads();
        }

        float gA[4] = {0.f,0.f,0.f,0.f}, gB[4] = {0.f,0.f,0.f,0.f};
        if (s > 0) {
            *(float4*)gA = *(const float4*)&Gs[bl * 68 + jl * 4];
            *(float4*)gB = *(const float4*)&Gs[(bl + 16) * 68 + jl * 4];
        }
        const int wC = (j0 + jl) >> 1, half = jl & 1;
        {
            float iv = fast_sig(gA[0] + xa[0]), fv = fast_sig(gA[1] + xa[1]);
            float gv = fast_tanh(gA[2] + xa[2]), ov = fast_sig(gA[3] + xa[3]);
            cA = fv * cA + iv * gv;
            float hv = ov * fast_tanh(cA);
            hbuf[((size_t)(t * 256 + b0 + bl)) * 256 + j0 + jl] = hv;
            store_split(g_hsp_h, g_hsp_l, (size_t)(t * 256 + b0 + bl) * 128 + wC, half, hv);
        }
        {
            float iv = fast_sig(gB[0] + xb[0]), fv = fast_sig(gB[1] + xb[1]);
            float gv = fast_tanh(gB[2] + xb[2]), ov = fast_sig(gB[3] + xb[3]);
            cB = fv * cB + iv * gv;
            float hv = ov * fast_tanh(cB);
            hbuf[((size_t)(t * 256 + b0 + bl + 16)) * 256 + j0 + jl] = hv;
            store_split(g_hsp_h, g_hsp_l, (size_t)(t * 256 + b0 + bl + 16) * 128 + wC, half, hv);
        }
        __syncthreads();
        if (tid == 0) flag_release(fb + s * 16 + jj);
    }
}

// ---------------- LayerNorm over last dim (256), warp per row ----------------
template<int WHICH>
__global__ void __launch_bounds__(256) ln_kernel(const float* __restrict__ gam,
                                                 const float* __restrict__ bet)
{
    const int warp = threadIdx.x >> 5, lane = threadIdx.x & 31;
    const size_t row = (size_t)blockIdx.x * 8 + warp;
    const float* x = (WHICH == 1) ? g_bl : g_h1;
    float* out = (WHICH == 1) ? g_bl : g_h1;
    const size_t base = row * 256 + lane * 8;

    float4 a0 = *(const float4*)(x + base);
    float4 a1 = *(const float4*)(x + base + 4);
    if (WHICH == 2) {
        float4 r0 = *(const float4*)(g_bl + base);
        float4 r1 = *(const float4*)(g_bl + base + 4);
        a0.x += r0.x; a0.y += r0.y; a0.z += r0.z; a0.w += r0.w;
        a1.x += r1.x; a1.y += r1.y; a1.z += r1.z; a1.w += r1.w;
    }
    float v[8] = {a0.x,a0.y,a0.z,a0.w,a1.x,a1.y,a1.z,a1.w};
    float s = 0.f;
#pragma unroll
    for (int i = 0; i < 8; i++) s += v[i];
#pragma unroll
    for (int o = 16; o; o >>= 1) s += __shfl_xor_sync(0xffffffffu, s, o);
    float mu = s * (1.f / 256.f);
    float ss = 0.f;
#pragma unroll
    for (int i = 0; i < 8; i++) { v[i] -= mu; ss += v[i] * v[i]; }
#pragma unroll
    for (int o = 16; o; o >>= 1) ss += __shfl_xor_sync(0xffffffffu, ss, o);
    float rs = rsqrtf(ss * (1.f / 256.f) + 1e-5f);
    const int c0 = lane * 8;
    float4 g0 = *(const float4*)(gam + c0), g1 = *(const float4*)(gam + c0 + 4);
    float4 b0 = *(const float4*)(bet + c0), b1 = *(const float4*)(bet + c0 + 4);
    float gg[8] = {g0.x,g0.y,g0.z,g0.w,g1.x,g1.y,g1.z,g1.w};
    float bb[8] = {b0.x,b0.y,b0.z,b0.w,b1.x,b1.y,b1.z,b1.w};
    float4 o0, o1;
    o0.x = v[0]*rs*gg[0]+bb[0]; o0.y = v[1]*rs*gg[1]+bb[1];
    o0.z = v[2]*rs*gg[2]+bb[2]; o0.w = v[3]*rs*gg[3]+bb[3];
    o1.x = v[4]*rs*gg[4]+bb[4]; o1.y = v[5]*rs*gg[5]+bb[5];
    o1.z = v[6]*rs*gg[6]+bb[6]; o1.w = v[7]*rs*gg[7]+bb[7];
    *(float4*)(out + base) = o0;
    *(float4*)(out + base + 4) = o1;
}

// ---------------- gather + affine + relu (auto int32/int64 idx) ----------------
__global__ void __launch_bounds__(256) gather_kernel(const int* __restrict__ idx32,
                                                     const float* __restrict__ bn_g,
                                                     const float* __restrict__ bn_b,
                                                     float* __restrict__ out)
{
    __shared__ int sidx;
    const int b = blockIdx.x, j = threadIdx.x;
    if (j < 32) {
        int v = idx32[2 * j + 1];
        unsigned m = __ballot_sync(0xffffffffu, v != 0);
        if (j == 0) sidx = (m == 0) ? idx32[2 * b] : idx32[b];
    }
    __syncthreads();
    const int t = sidx;
    float scale = rsqrtf(1.0f + 1e-5f);
    float y = g_h2[((size_t)(t * 256 + b)) * 256 + j] * scale * bn_g[j] + bn_b[j];
    out[(size_t)b * 256 + j] = fmaxf(y, 0.f);
}

// ---------------- launch ----------------
extern "C" void kernel_launch(void* const* d_in, const int* in_sizes, int n_in,
                              void* d_out, int out_size)
{
    const float* inp   = (const float*)d_in[0];
    const int*   idx   = (const int*)  d_in[1];
    const float* Wih_f = (const float*)d_in[2];
    const float* Whh_f = (const float*)d_in[3];
    const float* b_f   = (const float*)d_in[4];
    const float* Wih_r = (const float*)d_in[5];
    const float* Whh_r = (const float*)d_in[6];
    const float* b_r   = (const float*)d_in[7];
    const float* ln1_g = (const float*)d_in[8];
    const float* ln1_b = (const float*)d_in[9];
    const float* W1ih  = (const float*)d_in[10];
    const float* W1hh  = (const float*)d_in[11];
    const float* b1    = (const float*)d_in[12];
    const float* ln2_g = (const float*)d_in[13];
    const float* ln2_b = (const float*)d_in[14];
    const float* W2ih  = (const float*)d_in[15];
    const float* W2hh  = (const float*)d_in[16];
    const float* b2    = (const float*)d_in[17];
    const float* bn_g  = (const float*)d_in[18];
    const float* bn_b  = (const float*)d_in[19];
    float* out = (float*)d_out;

    const int SMG = 16384 * 4;                                   // 64 KB gemm
    const int SM0 = (8192 * 2 + 1024 * 2) * 4 + 16 * 132 * 4;    // 82176
    const int SM1 = (8192 * 2 + 4096 * 2) * 4 + 32 * 68 * 4;     // 107008
    cudaFuncSetAttribute(mma_gemm<128, 512, 0>, cudaFuncAttributeMaxDynamicSharedMemorySize, SMG);
    cudaFuncSetAttribute(mma_gemm<128, 512, 1>, cudaFuncAttributeMaxDynamicSharedMemorySize, SMG);
    cudaFuncSetAttribute(mma_gemm<256, 1024, 2>, cudaFuncAttributeMaxDynamicSharedMemorySize, SMG);
    cudaFuncSetAttribute(mma_gemm<256, 1024, 3>, cudaFuncAttributeMaxDynamicSharedMemorySize, SMG);
    cudaFuncSetAttribute(scan0_kernel,      cudaFuncAttributeMaxDynamicSharedMemorySize, SM0);
    cudaFuncSetAttribute(scan256_kernel<1>, cudaFuncAttributeMaxDynamicSharedMemorySize, SM1);
    cudaFuncSetAttribute(scan256_kernel<2>, cudaFuncAttributeMaxDynamicSharedMemorySize, SM1);

    zero_flags_kernel<<<512, 256>>>();
    mma_gemm<128, 512, 0><<<dim3(512, 4), 256, SMG>>>(inp, Wih_f, b_f);
    mma_gemm<128, 512, 1><<<dim3(512, 4), 256, SMG>>>(inp, Wih_r, b_r);
    scan0_kernel<<<dim3(16, 4, 2), 256, SM0>>>(Whh_f, Whh_r);
    ln_kernel<1><<<8192, 256>>>(ln1_g, ln1_b);
    mma_gemm<256, 1024, 2><<<dim3(512, 8), 256, SMG>>>(nullptr, W1ih, b1);
    scan256_kernel<1><<<dim3(8, 16), 256, SM1>>>(W1hh);
    ln_kernel<2><<<8192, 256>>>(ln2_g, ln2_b);
    mma_gemm<256, 1024, 3><<<dim3(512, 8), 256, SMG>>>(nullptr, W2ih, b2);
    scan256_kernel<2><<<dim3(8, 16), 256, SM1>>>(W2hh);
    gather_kernel<<<256, 256>>>(idx, bn_g, bn_b, out);
}